// round 4
// baseline (speedup 1.0000x reference)
#include <cuda_runtime.h>

#define C_    19
#define HW_   (512*1024)
#define P_    (4*HW_)
#define TPB   256
#define PPT   4                       // pixels per thread (float4)
#define PPB   (TPB*PPT)               // 1024 pixels per block
#define GRID_ (P_/PPB)                // 2048 blocks
#define MIN_KEPT_ 256
#define THRESH_   0.7f

// ---- device scratch (zero-initialized at load; finalize resets after each call) ----
__device__ double g_sum_wnll;
__device__ double g_sum_w;
__device__ int    g_cnt_le;
__device__ int    g_num_valid;
__device__ int    g_ov_cnt;
__device__ int    g_done;
__device__ float  g_ov_pred[P_];
__device__ float  g_ov_wnll[P_];
__device__ float  g_ov_w[P_];

__global__ __launch_bounds__(TPB, 2)   // allow up to 128 regs/thread
void ohem_fused_kernel(const float* __restrict__ predict,
                       const int*   __restrict__ tgt,     // int32 or int64 (low words)
                       const float* __restrict__ cw,
                       float*       __restrict__ out)
{
    const int tid       = threadIdx.x;
    const int blockBase = blockIdx.x * PPB;
    const int wid = tid >> 5, lid = tid & 31;

    // ---- per-block target dtype detection (in-bounds for both widths) ----
    __shared__ int s_nz;
    if (tid == 0) s_nz = 0;
    __syncthreads();
    if (tid < 128) {
        int v = tgt[blockBase + 2 * tid + 1];
        if (v != 0 && v != -1) atomicOr(&s_nz, 1);
    }
    __syncthreads();
    const int stride = s_nz ? 1 : 2;

    // ---- phase 1: batch-load labels + ALL 19 class float4s (max MLP) ----
    const int p0 = blockBase + tid * PPT;
    const int n  = p0 >> 19;                 // p / HW_
    const int hw = p0 & (HW_ - 1);
    const float4* base =
        reinterpret_cast<const float4*>(predict + (size_t)n * (C_ * HW_) + hw);

    float4 v[C_];
#pragma unroll
    for (int c = 0; c < C_; c++)
        v[c] = __ldcs(&base[(size_t)c * (HW_ / 4)]);   // read-once: evict-first

    int lab[PPT];
#pragma unroll
    for (int j = 0; j < PPT; j++) lab[j] = tgt[(size_t)(p0 + j) * stride];

    // ---- phase 2: streaming softmax-sum + gt-logit capture ----
    float sum[PPT] = {0.f, 0.f, 0.f, 0.f};
    float xl[PPT]  = {0.f, 0.f, 0.f, 0.f};
#pragma unroll
    for (int c = 0; c < C_; c++) {
        sum[0] += __expf(v[c].x); if (lab[0] == c) xl[0] = v[c].x;
        sum[1] += __expf(v[c].y); if (lab[1] == c) xl[1] = v[c].y;
        sum[2] += __expf(v[c].z); if (lab[2] == c) xl[2] = v[c].z;
        sum[3] += __expf(v[c].w); if (lab[3] == c) xl[3] = v[c].w;
    }

    float wnll = 0.f, wv = 0.f;
    int   cle = 0, cval = 0;
#pragma unroll
    for (int j = 0; j < PPT; j++) {
        if (lab[j] >= 0) {                    // valid (not IGNORE=-1)
            cval++;
            float lse = __logf(sum[j]);
            float nll = lse - xl[j];          // -log p(gt)
            float pr  = __expf(-nll);         // p(gt)
            float w   = cw[lab[j]];
            float wn  = w * nll;
            if (pr <= THRESH_) { cle++; wnll += wn; wv += w; }
            else {
                int i = atomicAdd(&g_ov_cnt, 1);   // rare: pred > 0.7
                g_ov_pred[i] = pr;
                g_ov_wnll[i] = wn;
                g_ov_w[i]    = w;
                __threadfence();
            }
        }
    }

    // ---- block reduction (8 warps) ----
#pragma unroll
    for (int o = 16; o > 0; o >>= 1) {
        wnll += __shfl_xor_sync(0xFFFFFFFFu, wnll, o);
        wv   += __shfl_xor_sync(0xFFFFFFFFu, wv,   o);
        cle  += __shfl_xor_sync(0xFFFFFFFFu, cle,  o);
        cval += __shfl_xor_sync(0xFFFFFFFFu, cval, o);
    }
    __shared__ float s_f0[8], s_f1[8];
    __shared__ int   s_i0[8], s_i1[8];
    if (lid == 0) { s_f0[wid] = wnll; s_f1[wid] = wv; s_i0[wid] = cle; s_i1[wid] = cval; }
    __syncthreads();

    __shared__ int s_last;
    if (wid == 0) {
        wnll = (lid < 8) ? s_f0[lid] : 0.f;
        wv   = (lid < 8) ? s_f1[lid] : 0.f;
        cle  = (lid < 8) ? s_i0[lid] : 0;
        cval = (lid < 8) ? s_i1[lid] : 0;
#pragma unroll
        for (int o = 4; o > 0; o >>= 1) {
            wnll += __shfl_xor_sync(0xFFFFFFFFu, wnll, o);
            wv   += __shfl_xor_sync(0xFFFFFFFFu, wv,   o);
            cle  += __shfl_xor_sync(0xFFFFFFFFu, cle,  o);
            cval += __shfl_xor_sync(0xFFFFFFFFu, cval, o);
        }
        if (lid == 0) {
            atomicAdd(&g_sum_wnll, (double)wnll);
            atomicAdd(&g_sum_w,    (double)wv);
            atomicAdd(&g_cnt_le,    cle);
            atomicAdd(&g_num_valid, cval);
            __threadfence();
            int t = atomicAdd(&g_done, 1);
            s_last = (t == GRID_ - 1);
        }
    }
    __syncthreads();
    if (!s_last) return;

    // ================= last block: finalize =================
    __shared__ double sd_sn, sd_sw;
    __shared__ int    si_c, si_nv, si_ov;
    if (tid == 0) {
        sd_sn = atomicAdd(&g_sum_wnll, 0.0);
        sd_sw = atomicAdd(&g_sum_w,    0.0);
        si_c  = atomicAdd(&g_cnt_le,    0);
        si_nv = atomicAdd(&g_num_valid, 0);
        si_ov = atomicAdd(&g_ov_cnt,    0);
        // reset ALL state for the next graph replay
        g_sum_wnll = 0.0; g_sum_w = 0.0;
        g_cnt_le = 0; g_num_valid = 0; g_ov_cnt = 0; g_done = 0;
    }
    __syncthreads();
    const double sn = sd_sn, sw = sd_sw;
    const int c = si_c, nv = si_nv, ov = si_ov;

    if (nv > MIN_KEPT_ && c >= MIN_KEPT_) {   // common case: threshold = 0.7
        if (tid == 0) out[0] = (float)(sn / sw);
        return;
    }

    // General case: nv <= MIN_KEPT -> keep all valid; else exact radix-select
    // of the kth-smallest pred among the overflow (>0.7) list.
    unsigned kbits = 0xFFFFFFFFu;
    __shared__ int      hist[256];
    __shared__ unsigned s_prefix;
    __shared__ int      s_rank;
    if (nv > MIN_KEPT_) {
        int rank = MIN_KEPT_ - 1 - c;           // 0-indexed rank within overflow
        unsigned prefix = 0;
        for (int shift = 24; shift >= 0; shift -= 8) {
            hist[tid] = 0;                      // TPB == 256
            __syncthreads();
            unsigned himask = (shift == 24) ? 0u : (0xFFFFFFFFu << (shift + 8));
            for (int i = tid; i < ov; i += TPB) {
                unsigned b = __float_as_uint(__ldcg(&g_ov_pred[i]));
                if ((b & himask) == prefix)
                    atomicAdd(&hist[(b >> shift) & 0xFF], 1);
            }
            __syncthreads();
            if (tid == 0) {
                int acc = 0, j = 0;
                for (; j < 256; j++) {
                    if (acc + hist[j] > rank) break;
                    acc += hist[j];
                }
                s_prefix = prefix | ((unsigned)j << shift);
                s_rank   = rank - acc;
            }
            __syncthreads();
            prefix = s_prefix;
            rank   = s_rank;
            __syncthreads();
        }
        kbits = prefix;   // pred <= kth  <=>  bits <= kbits (positive floats)
    }

    float en = 0.f, ew = 0.f;
    for (int i = tid; i < ov; i += TPB) {
        unsigned b = __float_as_uint(__ldcg(&g_ov_pred[i]));
        if (b <= kbits) { en += __ldcg(&g_ov_wnll[i]); ew += __ldcg(&g_ov_w[i]); }
    }
#pragma unroll
    for (int o = 16; o > 0; o >>= 1) {
        en += __shfl_xor_sync(0xFFFFFFFFu, en, o);
        ew += __shfl_xor_sync(0xFFFFFFFFu, ew, o);
    }
    if (lid == 0) { s_f0[wid] = en; s_f1[wid] = ew; }
    __syncthreads();
    if (tid == 0) {
        float ten = 0.f, tew = 0.f;
        for (int k = 0; k < 8; k++) { ten += s_f0[k]; tew += s_f1[k]; }
        out[0] = (float)((sn + (double)ten) / (sw + (double)tew));
    }
}

// ---------------------------------------------------------------------------
extern "C" void kernel_launch(void* const* d_in, const int* in_sizes, int n_in,
                              void* d_out, int out_size) {
    const float* predict = (const float*)d_in[0];
    const int*   target  = (const int*)d_in[1];
    const float* cw      = (const float*)d_in[2];
    float*       out     = (float*)d_out;

    ohem_fused_kernel<<<GRID_, TPB>>>(predict, target, cw, out);
}

// round 5
// speedup vs baseline: 1.4784x; 1.4784x over previous
#include <cuda_runtime.h>

#define C_    19
#define CH0   10                      // first load chunk
#define CH1   (C_ - CH0)              // second load chunk (9)
#define HW_   (512*1024)
#define P_    (4*HW_)
#define TPB   256
#define PPT   4                       // pixels per thread (float4)
#define PPB   (TPB*PPT)               // 1024 pixels per block
#define GRID_ (P_/PPB)                // 2048 blocks
#define MIN_KEPT_ 256
#define THRESH_   0.7f

// ---- device scratch (zero-initialized at load; finalize resets after each call) ----
__device__ double g_sum_wnll;
__device__ double g_sum_w;
__device__ int    g_cnt_le;
__device__ int    g_num_valid;
__device__ int    g_ov_cnt;
__device__ int    g_done;
__device__ float  g_ov_pred[P_];
__device__ float  g_ov_wnll[P_];
__device__ float  g_ov_w[P_];

__global__ __launch_bounds__(TPB, 4)   // cap 64 regs -> 4 CTAs/SM, 50% occ
void ohem_fused_kernel(const float* __restrict__ predict,
                       const int*   __restrict__ tgt,     // int32 or int64 (low words)
                       const float* __restrict__ cw,
                       float*       __restrict__ out)
{
    const int tid       = threadIdx.x;
    const int blockBase = blockIdx.x * PPB;
    const int wid = tid >> 5, lid = tid & 31;

    // ---- per-block target dtype detection (in-bounds for both widths) ----
    __shared__ int s_nz;
    if (tid == 0) s_nz = 0;
    __syncthreads();
    if (tid < 128) {
        int v = tgt[blockBase + 2 * tid + 1];
        if (v != 0 && v != -1) atomicOr(&s_nz, 1);
    }
    __syncthreads();
    const int stride = s_nz ? 1 : 2;

    const int p0 = blockBase + tid * PPT;
    const int n  = p0 >> 19;                 // p / HW_
    const int hw = p0 & (HW_ - 1);
    const float4* base =
        reinterpret_cast<const float4*>(predict + (size_t)n * (C_ * HW_) + hw);

    int lab[PPT];
#pragma unroll
    for (int j = 0; j < PPT; j++) lab[j] = tgt[(size_t)(p0 + j) * stride];

    float sum[PPT] = {0.f, 0.f, 0.f, 0.f};
    float xl[PPT]  = {0.f, 0.f, 0.f, 0.f};

    // ---- chunk 0: batch-load 10 float4s, then process ----
    {
        float4 v[CH0];
#pragma unroll
        for (int c = 0; c < CH0; c++)
            v[c] = __ldcs(&base[(size_t)c * (HW_ / 4)]);   // read-once: evict-first
#pragma unroll
        for (int c = 0; c < CH0; c++) {
            sum[0] += __expf(v[c].x); if (lab[0] == c) xl[0] = v[c].x;
            sum[1] += __expf(v[c].y); if (lab[1] == c) xl[1] = v[c].y;
            sum[2] += __expf(v[c].z); if (lab[2] == c) xl[2] = v[c].z;
            sum[3] += __expf(v[c].w); if (lab[3] == c) xl[3] = v[c].w;
        }
    }
    // ---- chunk 1: batch-load 9 float4s, then process ----
    {
        float4 v[CH1];
#pragma unroll
        for (int c = 0; c < CH1; c++)
            v[c] = __ldcs(&base[(size_t)(CH0 + c) * (HW_ / 4)]);
#pragma unroll
        for (int c = 0; c < CH1; c++) {
            const int cc = CH0 + c;
            sum[0] += __expf(v[c].x); if (lab[0] == cc) xl[0] = v[c].x;
            sum[1] += __expf(v[c].y); if (lab[1] == cc) xl[1] = v[c].y;
            sum[2] += __expf(v[c].z); if (lab[2] == cc) xl[2] = v[c].z;
            sum[3] += __expf(v[c].w); if (lab[3] == cc) xl[3] = v[c].w;
        }
    }

    float wnll = 0.f, wv = 0.f;
    int   cle = 0, cval = 0;
#pragma unroll
    for (int j = 0; j < PPT; j++) {
        if (lab[j] >= 0) {                    // valid (not IGNORE=-1)
            cval++;
            float lse = __logf(sum[j]);
            float nll = lse - xl[j];          // -log p(gt)
            float pr  = __expf(-nll);         // p(gt)
            float w   = cw[lab[j]];
            float wn  = w * nll;
            if (pr <= THRESH_) { cle++; wnll += wn; wv += w; }
            else {
                int i = atomicAdd(&g_ov_cnt, 1);   // rare: pred > 0.7
                g_ov_pred[i] = pr;
                g_ov_wnll[i] = wn;
                g_ov_w[i]    = w;
                __threadfence();
            }
        }
    }

    // ---- block reduction (8 warps) ----
#pragma unroll
    for (int o = 16; o > 0; o >>= 1) {
        wnll += __shfl_xor_sync(0xFFFFFFFFu, wnll, o);
        wv   += __shfl_xor_sync(0xFFFFFFFFu, wv,   o);
        cle  += __shfl_xor_sync(0xFFFFFFFFu, cle,  o);
        cval += __shfl_xor_sync(0xFFFFFFFFu, cval, o);
    }
    __shared__ float s_f0[8], s_f1[8];
    __shared__ int   s_i0[8], s_i1[8];
    if (lid == 0) { s_f0[wid] = wnll; s_f1[wid] = wv; s_i0[wid] = cle; s_i1[wid] = cval; }
    __syncthreads();

    __shared__ int s_last;
    if (wid == 0) {
        wnll = (lid < 8) ? s_f0[lid] : 0.f;
        wv   = (lid < 8) ? s_f1[lid] : 0.f;
        cle  = (lid < 8) ? s_i0[lid] : 0;
        cval = (lid < 8) ? s_i1[lid] : 0;
#pragma unroll
        for (int o = 4; o > 0; o >>= 1) {
            wnll += __shfl_xor_sync(0xFFFFFFFFu, wnll, o);
            wv   += __shfl_xor_sync(0xFFFFFFFFu, wv,   o);
            cle  += __shfl_xor_sync(0xFFFFFFFFu, cle,  o);
            cval += __shfl_xor_sync(0xFFFFFFFFu, cval, o);
        }
        if (lid == 0) {
            atomicAdd(&g_sum_wnll, (double)wnll);
            atomicAdd(&g_sum_w,    (double)wv);
            atomicAdd(&g_cnt_le,    cle);
            atomicAdd(&g_num_valid, cval);
            __threadfence();
            int t = atomicAdd(&g_done, 1);
            s_last = (t == GRID_ - 1);
        }
    }
    __syncthreads();
    if (!s_last) return;

    // ================= last block: finalize =================
    __shared__ double sd_sn, sd_sw;
    __shared__ int    si_c, si_nv, si_ov;
    if (tid == 0) {
        sd_sn = atomicAdd(&g_sum_wnll, 0.0);
        sd_sw = atomicAdd(&g_sum_w,    0.0);
        si_c  = atomicAdd(&g_cnt_le,    0);
        si_nv = atomicAdd(&g_num_valid, 0);
        si_ov = atomicAdd(&g_ov_cnt,    0);
        // reset ALL state for the next graph replay
        g_sum_wnll = 0.0; g_sum_w = 0.0;
        g_cnt_le = 0; g_num_valid = 0; g_ov_cnt = 0; g_done = 0;
    }
    __syncthreads();
    const double sn = sd_sn, sw = sd_sw;
    const int c = si_c, nv = si_nv, ov = si_ov;

    if (nv > MIN_KEPT_ && c >= MIN_KEPT_) {   // common case: threshold = 0.7
        if (tid == 0) out[0] = (float)(sn / sw);
        return;
    }

    // General case: nv <= MIN_KEPT -> keep all valid; else exact radix-select
    // of the kth-smallest pred among the overflow (>0.7) list.
    unsigned kbits = 0xFFFFFFFFu;
    __shared__ int      hist[256];
    __shared__ unsigned s_prefix;
    __shared__ int      s_rank;
    if (nv > MIN_KEPT_) {
        int rank = MIN_KEPT_ - 1 - c;           // 0-indexed rank within overflow
        unsigned prefix = 0;
        for (int shift = 24; shift >= 0; shift -= 8) {
            hist[tid] = 0;                      // TPB == 256
            __syncthreads();
            unsigned himask = (shift == 24) ? 0u : (0xFFFFFFFFu << (shift + 8));
            for (int i = tid; i < ov; i += TPB) {
                unsigned b = __float_as_uint(__ldcg(&g_ov_pred[i]));
                if ((b & himask) == prefix)
                    atomicAdd(&hist[(b >> shift) & 0xFF], 1);
            }
            __syncthreads();
            if (tid == 0) {
                int acc = 0, j = 0;
                for (; j < 256; j++) {
                    if (acc + hist[j] > rank) break;
                    acc += hist[j];
                }
                s_prefix = prefix | ((unsigned)j << shift);
                s_rank   = rank - acc;
            }
            __syncthreads();
            prefix = s_prefix;
            rank   = s_rank;
            __syncthreads();
        }
        kbits = prefix;   // pred <= kth  <=>  bits <= kbits (positive floats)
    }

    float en = 0.f, ew = 0.f;
    for (int i = tid; i < ov; i += TPB) {
        unsigned b = __float_as_uint(__ldcg(&g_ov_pred[i]));
        if (b <= kbits) { en += __ldcg(&g_ov_wnll[i]); ew += __ldcg(&g_ov_w[i]); }
    }
#pragma unroll
    for (int o = 16; o > 0; o >>= 1) {
        en += __shfl_xor_sync(0xFFFFFFFFu, en, o);
        ew += __shfl_xor_sync(0xFFFFFFFFu, ew, o);
    }
    if (lid == 0) { s_f0[wid] = en; s_f1[wid] = ew; }
    __syncthreads();
    if (tid == 0) {
        float ten = 0.f, tew = 0.f;
        for (int k = 0; k < 8; k++) { ten += s_f0[k]; tew += s_f1[k]; }
        out[0] = (float)((sn + (double)ten) / (sw + (double)tew));
    }
}

// ---------------------------------------------------------------------------
extern "C" void kernel_launch(void* const* d_in, const int* in_sizes, int n_in,
                              void* d_out, int out_size) {
    const float* predict = (const float*)d_in[0];
    const int*   target  = (const int*)d_in[1];
    const float* cw      = (const float*)d_in[2];
    float*       out     = (float*)d_out;

    ohem_fused_kernel<<<GRID_, TPB>>>(predict, target, cw, out);
}

// round 6
// speedup vs baseline: 1.8423x; 1.2462x over previous
#include <cuda_runtime.h>

#define C_    19
#define HW_   (512*1024)
#define P_    (4*HW_)
#define TPB   256
#define PPT   4                       // pixels per thread (one float4)
#define PPB   (TPB*PPT)               // 1024 pixels per block
#define GRID_ (P_/PPB)                // 2048 blocks
#define MIN_KEPT_ 256
#define THRESH_   0.7f
#define PLANE4 (HW_/4)                // float4 stride between class planes

// ---- device scratch (zero-initialized at load; finalize resets after each call) ----
__device__ double g_sum_wnll;
__device__ double g_sum_w;
__device__ int    g_cnt_le;
__device__ int    g_num_valid;
__device__ int    g_ov_cnt;
__device__ int    g_done;
__device__ float  g_ov_pred[P_];
__device__ float  g_ov_wnll[P_];
__device__ float  g_ov_w[P_];

__global__ __launch_bounds__(TPB, 6)   // 42-reg cap -> 6 CTAs/SM, 75% occ
void ohem_fused_kernel(const float* __restrict__ predict,
                       const int*   __restrict__ tgt,     // int32 or int64 (low words)
                       const float* __restrict__ cw,
                       float*       __restrict__ out)
{
    const int tid       = threadIdx.x;
    const int blockBase = blockIdx.x * PPB;
    const int wid = tid >> 5, lid = tid & 31;

    // ---- per-block target dtype detection (in-bounds for both widths) ----
    __shared__ int s_nz;
    if (tid == 0) s_nz = 0;
    __syncthreads();
    if (tid < 128) {
        int v = tgt[blockBase + 2 * tid + 1];
        if (v != 0 && v != -1) atomicOr(&s_nz, 1);
    }
    __syncthreads();
    const int stride = s_nz ? 1 : 2;

    const int p0 = blockBase + tid * PPT;
    const int n  = p0 >> 19;                 // p / HW_
    const int hw = p0 & (HW_ - 1);
    const float4* base =
        reinterpret_cast<const float4*>(predict + (size_t)n * (C_ * HW_) + hw);

    int lab[PPT];
#pragma unroll
    for (int j = 0; j < PPT; j++) lab[j] = tgt[(size_t)(p0 + j) * stride];

    float sum[PPT] = {0.f, 0.f, 0.f, 0.f};
    float xl[PPT]  = {0.f, 0.f, 0.f, 0.f};

    // ---- rolling pipeline over classes: prefetch c+2 while processing c ----
    float4 v0 = __ldcs(&base[0]);
    float4 v1 = __ldcs(&base[PLANE4]);
#pragma unroll
    for (int c = 0; c < C_; c++) {
        float4 nxt;
        if (c + 2 < C_) nxt = __ldcs(&base[(size_t)(c + 2) * PLANE4]);
        sum[0] += __expf(v0.x); if (lab[0] == c) xl[0] = v0.x;
        sum[1] += __expf(v0.y); if (lab[1] == c) xl[1] = v0.y;
        sum[2] += __expf(v0.z); if (lab[2] == c) xl[2] = v0.z;
        sum[3] += __expf(v0.w); if (lab[3] == c) xl[3] = v0.w;
        v0 = v1;
        v1 = nxt;
    }

    float wnll = 0.f, wv = 0.f;
    int   cle = 0, cval = 0;
#pragma unroll
    for (int j = 0; j < PPT; j++) {
        if (lab[j] >= 0) {                    // valid (not IGNORE=-1)
            cval++;
            float lse = __logf(sum[j]);
            float nll = lse - xl[j];          // -log p(gt)
            float pr  = __expf(-nll);         // p(gt)
            float w   = cw[lab[j]];
            float wn  = w * nll;
            if (pr <= THRESH_) { cle++; wnll += wn; wv += w; }
            else {
                int i = atomicAdd(&g_ov_cnt, 1);   // rare: pred > 0.7
                g_ov_pred[i] = pr;
                g_ov_wnll[i] = wn;
                g_ov_w[i]    = w;
                __threadfence();
            }
        }
    }

    // ---- block reduction (8 warps) ----
#pragma unroll
    for (int o = 16; o > 0; o >>= 1) {
        wnll += __shfl_xor_sync(0xFFFFFFFFu, wnll, o);
        wv   += __shfl_xor_sync(0xFFFFFFFFu, wv,   o);
        cle  += __shfl_xor_sync(0xFFFFFFFFu, cle,  o);
        cval += __shfl_xor_sync(0xFFFFFFFFu, cval, o);
    }
    __shared__ float s_f0[8], s_f1[8];
    __shared__ int   s_i0[8], s_i1[8];
    if (lid == 0) { s_f0[wid] = wnll; s_f1[wid] = wv; s_i0[wid] = cle; s_i1[wid] = cval; }
    __syncthreads();

    __shared__ int s_last;
    if (wid == 0) {
        wnll = (lid < 8) ? s_f0[lid] : 0.f;
        wv   = (lid < 8) ? s_f1[lid] : 0.f;
        cle  = (lid < 8) ? s_i0[lid] : 0;
        cval = (lid < 8) ? s_i1[lid] : 0;
#pragma unroll
        for (int o = 4; o > 0; o >>= 1) {
            wnll += __shfl_xor_sync(0xFFFFFFFFu, wnll, o);
            wv   += __shfl_xor_sync(0xFFFFFFFFu, wv,   o);
            cle  += __shfl_xor_sync(0xFFFFFFFFu, cle,  o);
            cval += __shfl_xor_sync(0xFFFFFFFFu, cval, o);
        }
        if (lid == 0) {
            atomicAdd(&g_sum_wnll, (double)wnll);
            atomicAdd(&g_sum_w,    (double)wv);
            atomicAdd(&g_cnt_le,    cle);
            atomicAdd(&g_num_valid, cval);
            __threadfence();
            int t = atomicAdd(&g_done, 1);
            s_last = (t == GRID_ - 1);
        }
    }
    __syncthreads();
    if (!s_last) return;

    // ================= last block: finalize =================
    __shared__ double sd_sn, sd_sw;
    __shared__ int    si_c, si_nv, si_ov;
    if (tid == 0) {
        sd_sn = atomicAdd(&g_sum_wnll, 0.0);
        sd_sw = atomicAdd(&g_sum_w,    0.0);
        si_c  = atomicAdd(&g_cnt_le,    0);
        si_nv = atomicAdd(&g_num_valid, 0);
        si_ov = atomicAdd(&g_ov_cnt,    0);
        // reset ALL state for the next graph replay
        g_sum_wnll = 0.0; g_sum_w = 0.0;
        g_cnt_le = 0; g_num_valid = 0; g_ov_cnt = 0; g_done = 0;
    }
    __syncthreads();
    const double sn = sd_sn, sw = sd_sw;
    const int c = si_c, nv = si_nv, ov = si_ov;

    if (nv > MIN_KEPT_ && c >= MIN_KEPT_) {   // common case: threshold = 0.7
        if (tid == 0) out[0] = (float)(sn / sw);
        return;
    }

    // General case: nv <= MIN_KEPT -> keep all valid; else exact radix-select
    // of the kth-smallest pred among the overflow (>0.7) list.
    unsigned kbits = 0xFFFFFFFFu;
    __shared__ int      hist[256];
    __shared__ unsigned s_prefix;
    __shared__ int      s_rank;
    if (nv > MIN_KEPT_) {
        int rank = MIN_KEPT_ - 1 - c;           // 0-indexed rank within overflow
        unsigned prefix = 0;
        for (int shift = 24; shift >= 0; shift -= 8) {
            hist[tid] = 0;                      // TPB == 256
            __syncthreads();
            unsigned himask = (shift == 24) ? 0u : (0xFFFFFFFFu << (shift + 8));
            for (int i = tid; i < ov; i += TPB) {
                unsigned b = __float_as_uint(__ldcg(&g_ov_pred[i]));
                if ((b & himask) == prefix)
                    atomicAdd(&hist[(b >> shift) & 0xFF], 1);
            }
            __syncthreads();
            if (tid == 0) {
                int acc = 0, j = 0;
                for (; j < 256; j++) {
                    if (acc + hist[j] > rank) break;
                    acc += hist[j];
                }
                s_prefix = prefix | ((unsigned)j << shift);
                s_rank   = rank - acc;
            }
            __syncthreads();
            prefix = s_prefix;
            rank   = s_rank;
            __syncthreads();
        }
        kbits = prefix;   // pred <= kth  <=>  bits <= kbits (positive floats)
    }

    float en = 0.f, ew = 0.f;
    for (int i = tid; i < ov; i += TPB) {
        unsigned b = __float_as_uint(__ldcg(&g_ov_pred[i]));
        if (b <= kbits) { en += __ldcg(&g_ov_wnll[i]); ew += __ldcg(&g_ov_w[i]); }
    }
#pragma unroll
    for (int o = 16; o > 0; o >>= 1) {
        en += __shfl_xor_sync(0xFFFFFFFFu, en, o);
        ew += __shfl_xor_sync(0xFFFFFFFFu, ew, o);
    }
    if (lid == 0) { s_f0[wid] = en; s_f1[wid] = ew; }
    __syncthreads();
    if (tid == 0) {
        float ten = 0.f, tew = 0.f;
        for (int k = 0; k < 8; k++) { ten += s_f0[k]; tew += s_f1[k]; }
        out[0] = (float)((sn + (double)ten) / (sw + (double)tew));
    }
}

// ---------------------------------------------------------------------------
extern "C" void kernel_launch(void* const* d_in, const int* in_sizes, int n_in,
                              void* d_out, int out_size) {
    const float* predict = (const float*)d_in[0];
    const int*   target  = (const int*)d_in[1];
    const float* cw      = (const float*)d_in[2];
    float*       out     = (float*)d_out;

    ohem_fused_kernel<<<GRID_, TPB>>>(predict, target, cw, out);
}

// round 7
// speedup vs baseline: 1.9631x; 1.0656x over previous
#include <cuda_runtime.h>

#define C_    19
#define HW_   (512*1024)
#define P_    (4*HW_)
#define TPB   256
#define NSM   148
#define CPS   6                        // CTAs per SM (one resident wave)
#define GRID_ (NSM*CPS)                // 888 persistent CTAs
#define NGRP  (P_/4)                   // float4 pixel-groups total
#define GSTRIDE (GRID_*TPB)            // grid-stride in groups
#define MIN_KEPT_ 256
#define THRESH_   0.7f
#define PLANE4 (HW_/4)                 // float4 stride between class planes

// ---- device scratch (zero-initialized at load; finalize resets after each call) ----
__device__ double g_sum_wnll;
__device__ double g_sum_w;
__device__ int    g_cnt_le;
__device__ int    g_num_valid;
__device__ int    g_ov_cnt;
__device__ int    g_done;
__device__ float  g_ov_pred[P_];
__device__ float  g_ov_wnll[P_];
__device__ float  g_ov_w[P_];

__global__ __launch_bounds__(TPB, CPS)   // ~42-reg cap -> 6 CTAs/SM resident
void ohem_fused_kernel(const float* __restrict__ predict,
                       const int*   __restrict__ tgt,     // int32 or int64 (low words)
                       const float* __restrict__ cw,
                       float*       __restrict__ out)
{
    const int tid = threadIdx.x;
    const int wid = tid >> 5, lid = tid & 31;

    // ---- per-CTA target dtype detection (in-bounds for both widths) ----
    __shared__ int s_nz;
    if (tid == 0) s_nz = 0;
    __syncthreads();
    {
        const int base = blockIdx.x * TPB;       // < P_ for all 888 CTAs
        if (tid < 128) {
            int v = tgt[base + 2 * tid + 1];
            if (v != 0 && v != -1) atomicOr(&s_nz, 1);
        }
    }
    __syncthreads();
    const int stride = s_nz ? 1 : 2;

    // ---- persistent grid-stride over float4 pixel-groups ----
    float wnll = 0.f, wv = 0.f;
    int   cle = 0, cval = 0;

    for (int g = blockIdx.x * TPB + tid; g < NGRP; g += GSTRIDE) {
        const int p0 = g * 4;
        const int n  = p0 >> 19;                 // p / HW_
        const int hw = p0 & (HW_ - 1);
        const float4* base =
            reinterpret_cast<const float4*>(predict + (size_t)n * (C_ * HW_) + hw);

        int lab[4];
#pragma unroll
        for (int j = 0; j < 4; j++) lab[j] = tgt[(size_t)(p0 + j) * stride];

        float sum[4] = {0.f, 0.f, 0.f, 0.f};
        float xl[4]  = {0.f, 0.f, 0.f, 0.f};

        // rolling pipeline over classes: prefetch c+2 while processing c
        float4 v0 = __ldcs(&base[0]);
        float4 v1 = __ldcs(&base[PLANE4]);
#pragma unroll
        for (int c = 0; c < C_; c++) {
            float4 nxt;
            if (c + 2 < C_) nxt = __ldcs(&base[(size_t)(c + 2) * PLANE4]);
            sum[0] += __expf(v0.x); if (lab[0] == c) xl[0] = v0.x;
            sum[1] += __expf(v0.y); if (lab[1] == c) xl[1] = v0.y;
            sum[2] += __expf(v0.z); if (lab[2] == c) xl[2] = v0.z;
            sum[3] += __expf(v0.w); if (lab[3] == c) xl[3] = v0.w;
            v0 = v1;
            v1 = nxt;
        }

#pragma unroll
        for (int j = 0; j < 4; j++) {
            if (lab[j] >= 0) {                    // valid (not IGNORE=-1)
                cval++;
                float lse = __logf(sum[j]);
                float nll = lse - xl[j];          // -log p(gt)
                float pr  = __expf(-nll);         // p(gt)
                float w   = cw[lab[j]];
                float wn  = w * nll;
                if (pr <= THRESH_) { cle++; wnll += wn; wv += w; }
                else {
                    int i = atomicAdd(&g_ov_cnt, 1);   // rare: pred > 0.7
                    g_ov_pred[i] = pr;
                    g_ov_wnll[i] = wn;
                    g_ov_w[i]    = w;
                    __threadfence();
                }
            }
        }
    }

    // ---- once-per-CTA block reduction (8 warps) ----
#pragma unroll
    for (int o = 16; o > 0; o >>= 1) {
        wnll += __shfl_xor_sync(0xFFFFFFFFu, wnll, o);
        wv   += __shfl_xor_sync(0xFFFFFFFFu, wv,   o);
        cle  += __shfl_xor_sync(0xFFFFFFFFu, cle,  o);
        cval += __shfl_xor_sync(0xFFFFFFFFu, cval, o);
    }
    __shared__ float s_f0[8], s_f1[8];
    __shared__ int   s_i0[8], s_i1[8];
    if (lid == 0) { s_f0[wid] = wnll; s_f1[wid] = wv; s_i0[wid] = cle; s_i1[wid] = cval; }
    __syncthreads();

    __shared__ int s_last;
    if (wid == 0) {
        wnll = (lid < 8) ? s_f0[lid] : 0.f;
        wv   = (lid < 8) ? s_f1[lid] : 0.f;
        cle  = (lid < 8) ? s_i0[lid] : 0;
        cval = (lid < 8) ? s_i1[lid] : 0;
#pragma unroll
        for (int o = 4; o > 0; o >>= 1) {
            wnll += __shfl_xor_sync(0xFFFFFFFFu, wnll, o);
            wv   += __shfl_xor_sync(0xFFFFFFFFu, wv,   o);
            cle  += __shfl_xor_sync(0xFFFFFFFFu, cle,  o);
            cval += __shfl_xor_sync(0xFFFFFFFFu, cval, o);
        }
        if (lid == 0) {
            atomicAdd(&g_sum_wnll, (double)wnll);
            atomicAdd(&g_sum_w,    (double)wv);
            atomicAdd(&g_cnt_le,    cle);
            atomicAdd(&g_num_valid, cval);
            __threadfence();
            int t = atomicAdd(&g_done, 1);
            s_last = (t == GRID_ - 1);
        }
    }
    __syncthreads();
    if (!s_last) return;

    // ================= last CTA: finalize =================
    __shared__ double sd_sn, sd_sw;
    __shared__ int    si_c, si_nv, si_ov;
    if (tid == 0) {
        sd_sn = atomicAdd(&g_sum_wnll, 0.0);
        sd_sw = atomicAdd(&g_sum_w,    0.0);
        si_c  = atomicAdd(&g_cnt_le,    0);
        si_nv = atomicAdd(&g_num_valid, 0);
        si_ov = atomicAdd(&g_ov_cnt,    0);
        // reset ALL state for the next graph replay
        g_sum_wnll = 0.0; g_sum_w = 0.0;
        g_cnt_le = 0; g_num_valid = 0; g_ov_cnt = 0; g_done = 0;
    }
    __syncthreads();
    const double sn = sd_sn, sw = sd_sw;
    const int c = si_c, nv = si_nv, ov = si_ov;

    if (nv > MIN_KEPT_ && c >= MIN_KEPT_) {   // common case: threshold = 0.7
        if (tid == 0) out[0] = (float)(sn / sw);
        return;
    }

    // General case: nv <= MIN_KEPT -> keep all valid; else exact radix-select
    // of the kth-smallest pred among the overflow (>0.7) list.
    unsigned kbits = 0xFFFFFFFFu;
    __shared__ int      hist[256];
    __shared__ unsigned s_prefix;
    __shared__ int      s_rank;
    if (nv > MIN_KEPT_) {
        int rank = MIN_KEPT_ - 1 - c;           // 0-indexed rank within overflow
        unsigned prefix = 0;
        for (int shift = 24; shift >= 0; shift -= 8) {
            hist[tid] = 0;                      // TPB == 256
            __syncthreads();
            unsigned himask = (shift == 24) ? 0u : (0xFFFFFFFFu << (shift + 8));
            for (int i = tid; i < ov; i += TPB) {
                unsigned b = __float_as_uint(__ldcg(&g_ov_pred[i]));
                if ((b & himask) == prefix)
                    atomicAdd(&hist[(b >> shift) & 0xFF], 1);
            }
            __syncthreads();
            if (tid == 0) {
                int acc = 0, j = 0;
                for (; j < 256; j++) {
                    if (acc + hist[j] > rank) break;
                    acc += hist[j];
                }
                s_prefix = prefix | ((unsigned)j << shift);
                s_rank   = rank - acc;
            }
            __syncthreads();
            prefix = s_prefix;
            rank   = s_rank;
            __syncthreads();
        }
        kbits = prefix;   // pred <= kth  <=>  bits <= kbits (positive floats)
    }

    float en = 0.f, ew = 0.f;
    for (int i = tid; i < ov; i += TPB) {
        unsigned b = __float_as_uint(__ldcg(&g_ov_pred[i]));
        if (b <= kbits) { en += __ldcg(&g_ov_wnll[i]); ew += __ldcg(&g_ov_w[i]); }
    }
#pragma unroll
    for (int o = 16; o > 0; o >>= 1) {
        en += __shfl_xor_sync(0xFFFFFFFFu, en, o);
        ew += __shfl_xor_sync(0xFFFFFFFFu, ew, o);
    }
    if (lid == 0) { s_f0[wid] = en; s_f1[wid] = ew; }
    __syncthreads();
    if (tid == 0) {
        float ten = 0.f, tew = 0.f;
        for (int k = 0; k < 8; k++) { ten += s_f0[k]; tew += s_f1[k]; }
        out[0] = (float)((sn + (double)ten) / (sw + (double)tew));
    }
}

// ---------------------------------------------------------------------------
extern "C" void kernel_launch(void* const* d_in, const int* in_sizes, int n_in,
                              void* d_out, int out_size) {
    const float* predict = (const float*)d_in[0];
    const int*   target  = (const int*)d_in[1];
    const float* cw      = (const float*)d_in[2];
    float*       out     = (float*)d_out;

    ohem_fused_kernel<<<GRID_, TPB>>>(predict, target, cw, out);
}